// round 7
// baseline (speedup 1.0000x reference)
#include <cuda_runtime.h>
#include <cuda_bf16.h>
#include <math.h>
#include <stdint.h>

// ---------------- problem constants ----------------
#define NROWS 4096      // 2*B
#define D     512
#define HALF  2048      // B
#define PSLOTS 64       // 32 column tiles * 2 halves
#define FBLOCKS 128     // finalize blocks

// ---------------- device scratch (no allocs) ----------------
__device__ __nv_bfloat16 g_zbf[NROWS * D];     // normalized rows, bf16 (4 MB)
__device__ float g_partial[NROWS * PSLOTS];    // exp row-sum partials (1 MB)
__device__ float g_pos[NROWS];
__device__ float g_diag[NROWS];
__device__ float g_blk[FBLOCKS];
__device__ int   g_cnt;                         // zero-init, self-resetting

// SMEM: THREE buffers, each A[128][72] + B[128][72] bf16
#define TILE_ELEMS (128 * 72)
#define BUF_BYTES  (2 * TILE_ELEMS * 2)  // 36864
#define SMEM_TOT   (3 * BUF_BYTES)       // 110592

__device__ __forceinline__ uint32_t smem_u32(const void* p) {
    uint32_t a;
    asm("{ .reg .u64 t; cvta.to.shared.u64 t, %1; cvt.u32.u64 %0, t; }" : "=r"(a) : "l"(p));
    return a;
}

// exp(2*s) for s in [-1,1]: (Taylor5(s/2))^4 — FMA pipe only.
__device__ __forceinline__ float exp2S(float s) {
    float y = 0.5f * s;
    float p = fmaf(y, 8.3333333e-3f, 4.1666667e-2f);
    p = fmaf(p, y, 1.6666667e-1f);
    p = fmaf(p, y, 0.5f);
    p = fmaf(p, y, 1.0f);
    p = fmaf(p, y, 1.0f);
    p = p * p;
    return p * p;
}

__device__ __forceinline__ float warp_xor_sum(float v) {
    #pragma unroll
    for (int o = 16; o > 0; o >>= 1)
        v += __shfl_xor_sync(0xffffffffu, v, o);
    return v;
}

// ============================================================
// Kernel 1: normalize + pos/diag. TWO warps per pair (row split
// in halves) -> 4096 warps, 2x occupancy vs warp-per-pair.
// Block = 256 threads = 8 warps = 4 pairs.
// ============================================================
__global__ void __launch_bounds__(256) normpos_k(const float* __restrict__ zi,
                                                 const float* __restrict__ zj)
{
    const int warp = threadIdx.x >> 5;
    const int lane = threadIdx.x & 31;
    const int pl = warp >> 1;                 // pair-in-block 0..3
    const int h  = warp & 1;                  // row half 0/1
    const int r = blockIdx.x * 4 + pl;        // pair index

    const float4* ra4 = reinterpret_cast<const float4*>(zi + (size_t)r * D) + h * 64;
    const float4* rb4 = reinterpret_cast<const float4*>(zj + (size_t)r * D) + h * 64;

    float4 a[2], b[2];
    a[0] = ra4[lane]; a[1] = ra4[lane + 32];
    b[0] = rb4[lane]; b[1] = rb4[lane + 32];

    float sa = 0.0f, sb = 0.0f;
    #pragma unroll
    for (int q = 0; q < 2; q++) {
        sa += a[q].x * a[q].x + a[q].y * a[q].y + a[q].z * a[q].z + a[q].w * a[q].w;
        sb += b[q].x * b[q].x + b[q].y * b[q].y + b[q].z * b[q].z + b[q].w * b[q].w;
    }
    sa = warp_xor_sum(sa);
    sb = warp_xor_sum(sb);

    __shared__ float shA[4][2], shB[4][2];
    if (lane == 0) { shA[pl][h] = sa; shB[pl][h] = sb; }
    __syncthreads();
    const float invA = 1.0f / fmaxf(sqrtf(shA[pl][0] + shA[pl][1]), 1e-8f);
    const float invB = 1.0f / fmaxf(sqrtf(shB[pl][0] + shB[pl][1]), 1e-8f);

    uint2* da = reinterpret_cast<uint2*>(g_zbf + (size_t)r * D) + h * 64;
    uint2* db = reinterpret_cast<uint2*>(g_zbf + (size_t)(r + HALF) * D) + h * 64;

    float pp = 0.0f, dA = 0.0f, dB = 0.0f;
    #pragma unroll
    for (int q = 0; q < 2; q++) {
        __nv_bfloat162 a01 = __float22bfloat162_rn(make_float2(a[q].x * invA, a[q].y * invA));
        __nv_bfloat162 a23 = __float22bfloat162_rn(make_float2(a[q].z * invA, a[q].w * invA));
        __nv_bfloat162 b01 = __float22bfloat162_rn(make_float2(b[q].x * invB, b[q].y * invB));
        __nv_bfloat162 b23 = __float22bfloat162_rn(make_float2(b[q].z * invB, b[q].w * invB));

        uint2 ua, ub;
        ua.x = *reinterpret_cast<uint32_t*>(&a01); ua.y = *reinterpret_cast<uint32_t*>(&a23);
        ub.x = *reinterpret_cast<uint32_t*>(&b01); ub.y = *reinterpret_cast<uint32_t*>(&b23);
        da[lane + 32 * q] = ua;
        db[lane + 32 * q] = ub;

        float2 fa0 = __bfloat1622float2(a01), fa1 = __bfloat1622float2(a23);
        float2 fb0 = __bfloat1622float2(b01), fb1 = __bfloat1622float2(b23);
        pp += fa0.x * fb0.x + fa0.y * fb0.y + fa1.x * fb1.x + fa1.y * fb1.y;
        dA += fa0.x * fa0.x + fa0.y * fa0.y + fa1.x * fa1.x + fa1.y * fa1.y;
        dB += fb0.x * fb0.x + fb0.y * fb0.y + fb1.x * fb1.x + fb1.y * fb1.y;
    }
    pp = warp_xor_sum(pp);
    dA = warp_xor_sum(dA);
    dB = warp_xor_sum(dB);

    __shared__ float shP[4][2], shDA[4][2], shDB[4][2];
    if (lane == 0) { shP[pl][h] = pp; shDA[pl][h] = dA; shDB[pl][h] = dB; }
    __syncthreads();
    if (h == 0 && lane == 0) {
        float p4 = shP[pl][0] + shP[pl][1];
        g_pos[r] = p4; g_pos[r + HALF] = p4;
        g_diag[r] = shDA[pl][0] + shDA[pl][1];
        g_diag[r + HALF] = shDB[pl][0] + shDB[pl][1];
    }
}

// ============================================================
// Kernel 2: symmetric bf16 mma.sync GEMM, 3-stage cp.async
// pipeline. 2-D grid, lower triangle exits. Row-sums always;
// col-sums for off-diagonal tiles.
// ============================================================
__global__ void __launch_bounds__(256, 2) gemm_expsum_k()
{
    const int brow = blockIdx.y;
    const int bcol = blockIdx.x;
    if (brow > bcol) return;           // symmetry: skip lower triangle

    extern __shared__ __align__(128) char smem[];
    const uint32_t sbase = smem_u32(smem);

    const int tid  = threadIdx.x;
    const int lane = tid & 31;
    const int wid  = tid >> 5;
    const int warp_m = wid >> 1;
    const int warp_n = wid & 1;

    const __nv_bfloat16* Ab = g_zbf + (size_t)(brow * 128) * D;
    const __nv_bfloat16* Bb = g_zbf + (size_t)(bcol * 128) * D;

    auto load_chunk = [&](int c) {
        const uint32_t sa = sbase + (uint32_t)(c % 3) * BUF_BYTES;
        const uint32_t sb = sa + TILE_ELEMS * 2;
        const int k0 = c * 64;
        #pragma unroll
        for (int i = 0; i < 4; i++) {
            int idx = tid + i * 256;
            int row = idx >> 3, cc = idx & 7;
            uint32_t so = (uint32_t)(row * 72 + cc * 8) * 2u;
            const __nv_bfloat16* ga = Ab + (size_t)row * D + k0 + cc * 8;
            const __nv_bfloat16* gb = Bb + (size_t)row * D + k0 + cc * 8;
            asm volatile("cp.async.cg.shared.global [%0], [%1], 16;" :: "r"(sa + so), "l"(ga));
            asm volatile("cp.async.cg.shared.global [%0], [%1], 16;" :: "r"(sb + so), "l"(gb));
        }
        asm volatile("cp.async.commit_group;");
    };

    float acc[2][8][4];
    #pragma unroll
    for (int mf = 0; mf < 2; mf++)
        #pragma unroll
        for (int nf = 0; nf < 8; nf++)
            #pragma unroll
            for (int e = 0; e < 4; e++) acc[mf][nf][e] = 0.0f;

    load_chunk(0);
    load_chunk(1);

    #pragma unroll 1
    for (int c = 0; c < 8; c++) {
        if (c < 6) {
            load_chunk(c + 2);
            asm volatile("cp.async.wait_group 2;");
        } else if (c == 6) {
            asm volatile("cp.async.wait_group 1;");
        } else {
            asm volatile("cp.async.wait_group 0;");
        }
        __syncthreads();

        const uint32_t sa = sbase + (uint32_t)(c % 3) * BUF_BYTES;
        const uint32_t sb = sa + TILE_ELEMS * 2;

        #pragma unroll
        for (int k16 = 0; k16 < 4; k16++) {
            uint32_t a[2][4];
            #pragma unroll
            for (int mf = 0; mf < 2; mf++) {
                int row = warp_m * 32 + mf * 16 + (lane & 15);
                int col = k16 * 16 + (lane >> 4) * 8;
                uint32_t addr = sa + (uint32_t)(row * 72 + col) * 2u;
                asm volatile("ldmatrix.sync.aligned.m8n8.x4.shared.b16 {%0,%1,%2,%3},[%4];"
                    : "=r"(a[mf][0]), "=r"(a[mf][1]), "=r"(a[mf][2]), "=r"(a[mf][3])
                    : "r"(addr));
            }
            #pragma unroll
            for (int nf16 = 0; nf16 < 4; nf16++) {
                int sub = lane >> 3, wi = lane & 7;
                int nrow = warp_n * 64 + nf16 * 16 + ((sub & 2) ? 8 : 0) + wi;
                int kcol = k16 * 16 + ((sub & 1) ? 8 : 0);
                uint32_t addr = sb + (uint32_t)(nrow * 72 + kcol) * 2u;
                uint32_t b0, b1, b2, b3;
                asm volatile("ldmatrix.sync.aligned.m8n8.x4.shared.b16 {%0,%1,%2,%3},[%4];"
                    : "=r"(b0), "=r"(b1), "=r"(b2), "=r"(b3) : "r"(addr));
                #pragma unroll
                for (int mf = 0; mf < 2; mf++) {
                    float* c0 = acc[mf][2 * nf16];
                    float* c1 = acc[mf][2 * nf16 + 1];
                    asm volatile(
                        "mma.sync.aligned.m16n8k16.row.col.f32.bf16.bf16.f32 "
                        "{%0,%1,%2,%3},{%4,%5,%6,%7},{%8,%9},{%0,%1,%2,%3};"
                        : "+f"(c0[0]), "+f"(c0[1]), "+f"(c0[2]), "+f"(c0[3])
                        : "r"(a[mf][0]), "r"(a[mf][1]), "r"(a[mf][2]), "r"(a[mf][3]),
                          "r"(b0), "r"(b1));
                    asm volatile(
                        "mma.sync.aligned.m16n8k16.row.col.f32.bf16.bf16.f32 "
                        "{%0,%1,%2,%3},{%4,%5,%6,%7},{%8,%9},{%0,%1,%2,%3};"
                        : "+f"(c1[0]), "+f"(c1[1]), "+f"(c1[2]), "+f"(c1[3])
                        : "r"(a[mf][0]), "r"(a[mf][1]), "r"(a[mf][2]), "r"(a[mf][3]),
                          "r"(b2), "r"(b3));
                }
            }
        }
        __syncthreads();
    }

    // --- epilogue ---
    #pragma unroll
    for (int mf = 0; mf < 2; mf++)
        #pragma unroll
        for (int nf = 0; nf < 8; nf++)
            #pragma unroll
            for (int e = 0; e < 4; e++)
                acc[mf][nf][e] = exp2S(acc[mf][nf][e]);

    #pragma unroll
    for (int mf = 0; mf < 2; mf++) {
        float rlo = 0.0f, rhi = 0.0f;
        #pragma unroll
        for (int nf = 0; nf < 8; nf++) {
            rlo += acc[mf][nf][0] + acc[mf][nf][1];
            rhi += acc[mf][nf][2] + acc[mf][nf][3];
        }
        rlo += __shfl_xor_sync(0xffffffffu, rlo, 1);
        rlo += __shfl_xor_sync(0xffffffffu, rlo, 2);
        rhi += __shfl_xor_sync(0xffffffffu, rhi, 1);
        rhi += __shfl_xor_sync(0xffffffffu, rhi, 2);
        if ((lane & 3) == 0) {
            int r0 = brow * 128 + warp_m * 32 + mf * 16 + (lane >> 2);
            int slot = bcol * 2 + warp_n;
            g_partial[(size_t)r0 * PSLOTS + slot] = rlo;
            g_partial[(size_t)(r0 + 8) * PSLOTS + slot] = rhi;
        }
    }

    if (brow != bcol) {
        float cs[16];
        #pragma unroll
        for (int nf = 0; nf < 8; nf++)
            #pragma unroll
            for (int e = 0; e < 2; e++)
                cs[nf * 2 + e] = acc[0][nf][e] + acc[0][nf][e + 2]
                               + acc[1][nf][e] + acc[1][nf][e + 2];
        #pragma unroll
        for (int i = 0; i < 16; i++) {
            cs[i] += __shfl_xor_sync(0xffffffffu, cs[i], 4);
            cs[i] += __shfl_xor_sync(0xffffffffu, cs[i], 8);
            cs[i] += __shfl_xor_sync(0xffffffffu, cs[i], 16);
        }
        float* scol = reinterpret_cast<float*>(smem);  // [4][128]
        __syncthreads();
        if (lane < 4) {
            #pragma unroll
            for (int nf = 0; nf < 8; nf++)
                #pragma unroll
                for (int e = 0; e < 2; e++) {
                    int col = warp_n * 64 + (nf >> 1) * 16 + (nf & 1) * 8 + lane * 2 + e;
                    scol[warp_m * 128 + col] = cs[nf * 2 + e];
                }
        }
        __syncthreads();
        if (tid < 128) {
            float v = scol[0 * 128 + tid] + scol[1 * 128 + tid];
            g_partial[(size_t)(bcol * 128 + tid) * PSLOTS + brow * 2 + 0] = v;
        } else {
            int ccol = tid - 128;
            float v = scol[2 * 128 + ccol] + scol[3 * 128 + ccol];
            g_partial[(size_t)(bcol * 128 + ccol) * PSLOTS + brow * 2 + 1] = v;
        }
    }
}

// ============================================================
// Kernel 3: single fused finalize. Warp per row; last block
// does the deterministic final reduction and self-resets g_cnt.
// ============================================================
__global__ void __launch_bounds__(1024) finalize_k(float* __restrict__ out)
{
    const int warp = threadIdx.x >> 5;
    const int lane = threadIdx.x & 31;
    const int row  = blockIdx.x * 32 + warp;

    float2 v2 = reinterpret_cast<const float2*>(g_partial + (size_t)row * PSLOTS)[lane];
    float s = v2.x + v2.y;
    #pragma unroll
    for (int o = 16; o > 0; o >>= 1)
        s += __shfl_down_sync(0xffffffffu, s, o);

    __shared__ float red[32];
    if (lane == 0) {
        float pos = g_pos[row], diag = g_diag[row];
        float tot = s - exp2S(diag) + exp2S(pos);
        red[warp] = logf(tot) - 2.0f * pos;
    }
    __syncthreads();

    __shared__ bool amlast;
    if (threadIdx.x < 32) {
        float v = red[threadIdx.x];
        #pragma unroll
        for (int o = 16; o > 0; o >>= 1)
            v += __shfl_down_sync(0xffffffffu, v, o);
        if (threadIdx.x == 0) {
            g_blk[blockIdx.x] = v;
            __threadfence();
            int old = atomicAdd(&g_cnt, 1);
            amlast = (old == FBLOCKS - 1);
        }
    }
    __syncthreads();

    if (amlast && threadIdx.x < 32) {
        __threadfence();
        float v = 0.0f;
        #pragma unroll
        for (int q = 0; q < FBLOCKS / 32; q++)       // fixed order: deterministic
            v += g_blk[q * 32 + lane];
        #pragma unroll
        for (int o = 16; o > 0; o >>= 1)
            v += __shfl_down_sync(0xffffffffu, v, o);
        if (lane == 0) {
            out[0] = v / (float)NROWS;
            g_cnt = 0;                               // self-reset for next replay
        }
    }
}

// ============================================================
extern "C" void kernel_launch(void* const* d_in, const int* in_sizes, int n_in,
                              void* d_out, int out_size)
{
    const float* zi = (const float*)d_in[0];
    const float* zj = (const float*)d_in[1];
    float* out = (float*)d_out;

    cudaFuncSetAttribute(gemm_expsum_k,
                         cudaFuncAttributeMaxDynamicSharedMemorySize, SMEM_TOT);

    normpos_k<<<HALF / 4, 256>>>(zi, zj);
    dim3 grid(NROWS / 128, NROWS / 128);   // (32, 32), lower triangle exits
    gemm_expsum_k<<<grid, 256, SMEM_TOT>>>();
    finalize_k<<<FBLOCKS, 1024>>>(out);
}

// round 8
// speedup vs baseline: 1.0332x; 1.0332x over previous
#include <cuda_runtime.h>
#include <cuda_bf16.h>
#include <cuda_fp8.h>
#include <math.h>
#include <stdint.h>

// ---------------- problem constants ----------------
#define NROWS 4096      // 2*B
#define D     512
#define HALF  2048      // B
#define PSLOTS 64       // 32 column tiles * 2 halves
#define FBLOCKS 128     // finalize blocks
#define SCALE   16.0f   // fp8 pre-scale; S accumulator carries 256x
#define INVSS   (1.0f / 256.0f)

// ---------------- device scratch (no allocs) ----------------
__device__ uint8_t g_z8[NROWS * D];            // normalized rows, e4m3 x16 (2 MB)
__device__ float g_partial[NROWS * PSLOTS];    // exp row-sum partials (1 MB)
__device__ float g_pos[NROWS];                 // fp32-accurate positive dots
__device__ float g_diag[NROWS];                // fp8-consistent diagonal (true scale)
__device__ float g_blk[FBLOCKS];
__device__ int   g_cnt;                         // zero-init, self-resetting

// SMEM: two buffers, each A[128][144B] + B[128][144B] (128 fp8 + 16B pad)
#define ROWB 144
#define TILE_BYTES (128 * ROWB)          // 18432
#define BUF_BYTES  (2 * TILE_BYTES)      // 36864
#define SMEM_TOT   (2 * BUF_BYTES)       // 73728

__device__ __forceinline__ uint32_t smem_u32(const void* p) {
    uint32_t a;
    asm("{ .reg .u64 t; cvta.to.shared.u64 t, %1; cvt.u32.u64 %0, t; }" : "=r"(a) : "l"(p));
    return a;
}

// exp(2*s) for s in [-1,1]: (Taylor5(s/2))^4 — FMA pipe only.
__device__ __forceinline__ float exp2S(float s) {
    float y = 0.5f * s;
    float p = fmaf(y, 8.3333333e-3f, 4.1666667e-2f);
    p = fmaf(p, y, 1.6666667e-1f);
    p = fmaf(p, y, 0.5f);
    p = fmaf(p, y, 1.0f);
    p = fmaf(p, y, 1.0f);
    p = p * p;
    return p * p;
}
// same, for the 256x-scaled GEMM accumulator
__device__ __forceinline__ float exp2Sacc(float s) {
    float y = s * (0.5f * INVSS);
    float p = fmaf(y, 8.3333333e-3f, 4.1666667e-2f);
    p = fmaf(p, y, 1.6666667e-1f);
    p = fmaf(p, y, 0.5f);
    p = fmaf(p, y, 1.0f);
    p = fmaf(p, y, 1.0f);
    p = p * p;
    return p * p;
}

__device__ __forceinline__ float warp_xor_sum(float v) {
    #pragma unroll
    for (int o = 16; o > 0; o >>= 1)
        v += __shfl_xor_sync(0xffffffffu, v, o);
    return v;
}

// float2 -> e4m3x2 (packed u16), and back for diag consistency
__device__ __forceinline__ uint16_t f2_to_e4m3x2(float2 f) {
    return (uint16_t)__nv_cvt_float2_to_fp8x2(f, __NV_SATFINITE, __NV_E4M3);
}
__device__ __forceinline__ float2 e4m3x2_to_f2(uint16_t u) {
    __half2_raw hr = __nv_cvt_fp8x2_to_halfraw2((__nv_fp8x2_storage_t)u, __NV_E4M3);
    __half2 h = *reinterpret_cast<__half2*>(&hr);
    return __half22float2(h);
}

// ============================================================
// Kernel 1: normalize + pos/diag, warp-per-pair (round-6 form),
// emits e4m3 scaled by 16. pos from fp32 (reference-accurate);
// diag from round-tripped fp8 (cancels GEMM diagonal).
// ============================================================
__global__ void __launch_bounds__(256) normpos_k(const float* __restrict__ zi,
                                                 const float* __restrict__ zj)
{
    const int warp = threadIdx.x >> 5;
    const int lane = threadIdx.x & 31;
    const int r = blockIdx.x * 8 + warp;      // pair index 0..HALF-1

    const float4* ra4 = reinterpret_cast<const float4*>(zi + (size_t)r * D);
    const float4* rb4 = reinterpret_cast<const float4*>(zj + (size_t)r * D);

    float4 a[4], b[4];
    #pragma unroll
    for (int q = 0; q < 4; q++) {
        a[q] = ra4[lane + 32 * q];
        b[q] = rb4[lane + 32 * q];
    }

    float sa = 0.0f, sb = 0.0f;
    #pragma unroll
    for (int q = 0; q < 4; q++) {
        sa += a[q].x * a[q].x + a[q].y * a[q].y + a[q].z * a[q].z + a[q].w * a[q].w;
        sb += b[q].x * b[q].x + b[q].y * b[q].y + b[q].z * b[q].z + b[q].w * b[q].w;
    }
    sa = warp_xor_sum(sa);
    sb = warp_xor_sum(sb);
    const float invA = 1.0f / fmaxf(sqrtf(sa), 1e-8f);
    const float invB = 1.0f / fmaxf(sqrtf(sb), 1e-8f);
    const float qA = invA * SCALE;
    const float qB = invB * SCALE;

    uint32_t* da = reinterpret_cast<uint32_t*>(g_z8 + (size_t)r * D);
    uint32_t* db = reinterpret_cast<uint32_t*>(g_z8 + (size_t)(r + HALF) * D);

    float pp = 0.0f, dA = 0.0f, dB = 0.0f;
    #pragma unroll
    for (int q = 0; q < 4; q++) {
        // fp32-accurate positive dot (pre-quantization)
        pp += (a[q].x * invA) * (b[q].x * invB) + (a[q].y * invA) * (b[q].y * invB)
            + (a[q].z * invA) * (b[q].z * invB) + (a[q].w * invA) * (b[q].w * invB);

        uint16_t a01 = f2_to_e4m3x2(make_float2(a[q].x * qA, a[q].y * qA));
        uint16_t a23 = f2_to_e4m3x2(make_float2(a[q].z * qA, a[q].w * qA));
        uint16_t b01 = f2_to_e4m3x2(make_float2(b[q].x * qB, b[q].y * qB));
        uint16_t b23 = f2_to_e4m3x2(make_float2(b[q].z * qB, b[q].w * qB));

        da[lane + 32 * q] = (uint32_t)a01 | ((uint32_t)a23 << 16);
        db[lane + 32 * q] = (uint32_t)b01 | ((uint32_t)b23 << 16);

        // diag from the SAME fp8 values (scaled): matches GEMM diagonal
        float2 fa0 = e4m3x2_to_f2(a01), fa1 = e4m3x2_to_f2(a23);
        float2 fb0 = e4m3x2_to_f2(b01), fb1 = e4m3x2_to_f2(b23);
        dA += fa0.x * fa0.x + fa0.y * fa0.y + fa1.x * fa1.x + fa1.y * fa1.y;
        dB += fb0.x * fb0.x + fb0.y * fb0.y + fb1.x * fb1.x + fb1.y * fb1.y;
    }
    pp = warp_xor_sum(pp);
    dA = warp_xor_sum(dA);
    dB = warp_xor_sum(dB);
    if (lane == 0) {
        g_pos[r] = pp; g_pos[r + HALF] = pp;
        g_diag[r] = dA * INVSS;           // back to true scale
        g_diag[r + HALF] = dB * INVSS;
    }
}

// ============================================================
// Kernel 2: symmetric e4m3 mma.sync GEMM (m16n8k32). 2-D grid,
// lower triangle exits. K=512 in 4 double-buffered chunks of
// 128. Row-sums always; col-sums for off-diagonal tiles.
// ============================================================
__global__ void __launch_bounds__(256, 2) gemm_expsum_k()
{
    const int brow = blockIdx.y;
    const int bcol = blockIdx.x;
    if (brow > bcol) return;           // symmetry: skip lower triangle

    extern __shared__ __align__(128) char smem[];
    const uint32_t sbase = smem_u32(smem);

    const int tid  = threadIdx.x;
    const int lane = tid & 31;
    const int wid  = tid >> 5;
    const int warp_m = wid >> 1;
    const int warp_n = wid & 1;

    const uint8_t* Ab = g_z8 + (size_t)(brow * 128) * D;
    const uint8_t* Bb = g_z8 + (size_t)(bcol * 128) * D;

    auto load_chunk = [&](int c) {
        const uint32_t sa = sbase + (uint32_t)(c & 1) * BUF_BYTES;
        const uint32_t sb = sa + TILE_BYTES;
        const int k0 = c * 128;
        #pragma unroll
        for (int i = 0; i < 4; i++) {
            int idx = tid + i * 256;
            int row = idx >> 3, cc = idx & 7;     // 8 x 16B per 128-byte row
            uint32_t so = (uint32_t)(row * ROWB + cc * 16);
            const uint8_t* ga = Ab + (size_t)row * D + k0 + cc * 16;
            const uint8_t* gb = Bb + (size_t)row * D + k0 + cc * 16;
            asm volatile("cp.async.cg.shared.global [%0], [%1], 16;" :: "r"(sa + so), "l"(ga));
            asm volatile("cp.async.cg.shared.global [%0], [%1], 16;" :: "r"(sb + so), "l"(gb));
        }
        asm volatile("cp.async.commit_group;");
    };

    float acc[2][8][4];
    #pragma unroll
    for (int mf = 0; mf < 2; mf++)
        #pragma unroll
        for (int nf = 0; nf < 8; nf++)
            #pragma unroll
            for (int e = 0; e < 4; e++) acc[mf][nf][e] = 0.0f;

    load_chunk(0);

    #pragma unroll 1
    for (int c = 0; c < 4; c++) {
        if (c < 3) {
            load_chunk(c + 1);
            asm volatile("cp.async.wait_group 1;");
        } else {
            asm volatile("cp.async.wait_group 0;");
        }
        __syncthreads();

        const uint32_t sa = sbase + (uint32_t)(c & 1) * BUF_BYTES;
        const uint32_t sb = sa + TILE_BYTES;

        #pragma unroll
        for (int ks = 0; ks < 4; ks++) {          // k32 steps within 128-chunk
            uint32_t a[2][4];
            #pragma unroll
            for (int mf = 0; mf < 2; mf++) {
                int row = warp_m * 32 + mf * 16 + (lane & 15);
                int col = ks * 32 + (lane >> 4) * 16;   // fp8 bytes
                uint32_t addr = sa + (uint32_t)(row * ROWB + col);
                asm volatile("ldmatrix.sync.aligned.m8n8.x4.shared.b16 {%0,%1,%2,%3},[%4];"
                    : "=r"(a[mf][0]), "=r"(a[mf][1]), "=r"(a[mf][2]), "=r"(a[mf][3])
                    : "r"(addr));
            }
            #pragma unroll
            for (int nf16 = 0; nf16 < 4; nf16++) {
                int sub = lane >> 3, wi = lane & 7;
                int nrow = warp_n * 64 + nf16 * 16 + ((sub & 2) ? 8 : 0) + wi;
                int kcol = ks * 32 + ((sub & 1) ? 16 : 0);
                uint32_t addr = sb + (uint32_t)(nrow * ROWB + kcol);
                uint32_t b0, b1, b2, b3;
                asm volatile("ldmatrix.sync.aligned.m8n8.x4.shared.b16 {%0,%1,%2,%3},[%4];"
                    : "=r"(b0), "=r"(b1), "=r"(b2), "=r"(b3) : "r"(addr));
                #pragma unroll
                for (int mf = 0; mf < 2; mf++) {
                    float* c0 = acc[mf][2 * nf16];
                    float* c1 = acc[mf][2 * nf16 + 1];
                    asm volatile(
                        "mma.sync.aligned.m16n8k32.row.col.f32.e4m3.e4m3.f32 "
                        "{%0,%1,%2,%3},{%4,%5,%6,%7},{%8,%9},{%0,%1,%2,%3};"
                        : "+f"(c0[0]), "+f"(c0[1]), "+f"(c0[2]), "+f"(c0[3])
                        : "r"(a[mf][0]), "r"(a[mf][1]), "r"(a[mf][2]), "r"(a[mf][3]),
                          "r"(b0), "r"(b1));
                    asm volatile(
                        "mma.sync.aligned.m16n8k32.row.col.f32.e4m3.e4m3.f32 "
                        "{%0,%1,%2,%3},{%4,%5,%6,%7},{%8,%9},{%0,%1,%2,%3};"
                        : "+f"(c1[0]), "+f"(c1[1]), "+f"(c1[2]), "+f"(c1[3])
                        : "r"(a[mf][0]), "r"(a[mf][1]), "r"(a[mf][2]), "r"(a[mf][3]),
                          "r"(b2), "r"(b3));
                }
            }
        }
        __syncthreads();
    }

    // --- epilogue: exp of 256x-scaled acc ---
    #pragma unroll
    for (int mf = 0; mf < 2; mf++)
        #pragma unroll
        for (int nf = 0; nf < 8; nf++)
            #pragma unroll
            for (int e = 0; e < 4; e++)
                acc[mf][nf][e] = exp2Sacc(acc[mf][nf][e]);

    #pragma unroll
    for (int mf = 0; mf < 2; mf++) {
        float rlo = 0.0f, rhi = 0.0f;
        #pragma unroll
        for (int nf = 0; nf < 8; nf++) {
            rlo += acc[mf][nf][0] + acc[mf][nf][1];
            rhi += acc[mf][nf][2] + acc[mf][nf][3];
        }
        rlo += __shfl_xor_sync(0xffffffffu, rlo, 1);
        rlo += __shfl_xor_sync(0xffffffffu, rlo, 2);
        rhi += __shfl_xor_sync(0xffffffffu, rhi, 1);
        rhi += __shfl_xor_sync(0xffffffffu, rhi, 2);
        if ((lane & 3) == 0) {
            int r0 = brow * 128 + warp_m * 32 + mf * 16 + (lane >> 2);
            int slot = bcol * 2 + warp_n;
            g_partial[(size_t)r0 * PSLOTS + slot] = rlo;
            g_partial[(size_t)(r0 + 8) * PSLOTS + slot] = rhi;
        }
    }

    if (brow != bcol) {
        float cs[16];
        #pragma unroll
        for (int nf = 0; nf < 8; nf++)
            #pragma unroll
            for (int e = 0; e < 2; e++)
                cs[nf * 2 + e] = acc[0][nf][e] + acc[0][nf][e + 2]
                               + acc[1][nf][e] + acc[1][nf][e + 2];
        #pragma unroll
        for (int i = 0; i < 16; i++) {
            cs[i] += __shfl_xor_sync(0xffffffffu, cs[i], 4);
            cs[i] += __shfl_xor_sync(0xffffffffu, cs[i], 8);
            cs[i] += __shfl_xor_sync(0xffffffffu, cs[i], 16);
        }
        float* scol = reinterpret_cast<float*>(smem);  // [4][128]
        __syncthreads();
        if (lane < 4) {
            #pragma unroll
            for (int nf = 0; nf < 8; nf++)
                #pragma unroll
                for (int e = 0; e < 2; e++) {
                    int col = warp_n * 64 + (nf >> 1) * 16 + (nf & 1) * 8 + lane * 2 + e;
                    scol[warp_m * 128 + col] = cs[nf * 2 + e];
                }
        }
        __syncthreads();
        if (tid < 128) {
            float v = scol[0 * 128 + tid] + scol[1 * 128 + tid];
            g_partial[(size_t)(bcol * 128 + tid) * PSLOTS + brow * 2 + 0] = v;
        } else {
            int ccol = tid - 128;
            float v = scol[2 * 128 + ccol] + scol[3 * 128 + ccol];
            g_partial[(size_t)(bcol * 128 + ccol) * PSLOTS + brow * 2 + 1] = v;
        }
    }
}

// ============================================================
// Kernel 3: single fused finalize. Warp per row; last block
// does the deterministic final reduction and self-resets g_cnt.
// ============================================================
__global__ void __launch_bounds__(1024) finalize_k(float* __restrict__ out)
{
    const int warp = threadIdx.x >> 5;
    const int lane = threadIdx.x & 31;
    const int row  = blockIdx.x * 32 + warp;

    float2 v2 = reinterpret_cast<const float2*>(g_partial + (size_t)row * PSLOTS)[lane];
    float s = v2.x + v2.y;
    #pragma unroll
    for (int o = 16; o > 0; o >>= 1)
        s += __shfl_down_sync(0xffffffffu, s, o);

    __shared__ float red[32];
    if (lane == 0) {
        float pos = g_pos[row], diag = g_diag[row];
        float tot = s - exp2S(diag) + exp2S(pos);
        red[warp] = logf(tot) - 2.0f * pos;
    }
    __syncthreads();

    __shared__ bool amlast;
    if (threadIdx.x < 32) {
        float v = red[threadIdx.x];
        #pragma unroll
        for (int o = 16; o > 0; o >>= 1)
            v += __shfl_down_sync(0xffffffffu, v, o);
        if (threadIdx.x == 0) {
            g_blk[blockIdx.x] = v;
            __threadfence();
            int old = atomicAdd(&g_cnt, 1);
            amlast = (old == FBLOCKS - 1);
        }
    }
    __syncthreads();

    if (amlast && threadIdx.x < 32) {
        __threadfence();
        float v = 0.0f;
        #pragma unroll
        for (int q = 0; q < FBLOCKS / 32; q++)       // fixed order: deterministic
            v += g_blk[q * 32 + lane];
        #pragma unroll
        for (int o = 16; o > 0; o >>= 1)
            v += __shfl_down_sync(0xffffffffu, v, o);
        if (lane == 0) {
            out[0] = v / (float)NROWS;
            g_cnt = 0;                               // self-reset for next replay
        }
    }
}

// ============================================================
extern "C" void kernel_launch(void* const* d_in, const int* in_sizes, int n_in,
                              void* d_out, int out_size)
{
    const float* zi = (const float*)d_in[0];
    const float* zj = (const float*)d_in[1];
    float* out = (float*)d_out;

    cudaFuncSetAttribute(gemm_expsum_k,
                         cudaFuncAttributeMaxDynamicSharedMemorySize, SMEM_TOT);

    normpos_k<<<HALF / 8, 256>>>(zi, zj);
    dim3 grid(NROWS / 128, NROWS / 128);   // (32, 32), lower triangle exits
    gemm_expsum_k<<<grid, 256, SMEM_TOT>>>();
    finalize_k<<<FBLOCKS, 1024>>>(out);
}